// round 15
// baseline (speedup 1.0000x reference)
#include <cuda_runtime.h>
#include <cuda_bf16.h>
#include <cuda_fp16.h>
#include <cstdint>
#include <math.h>

#define NTOK   21760
#define BATCH  2
#define NQ     (NTOK*BATCH)
#define DIM    256
#define NLAY   6
#define DFFN   1024
#define QOUT   (NQ*DIM)

typedef __nv_bfloat16 bf16;

__device__ __constant__ int c_LW[4] = {128, 64, 32, 16};
__device__ __constant__ int c_LS[4] = {0, 16384, 20480, 21504};
__device__ __constant__ float c_tail[12] = {128.f,128.f,64.f,64.f,32.f,32.f,16.f,16.f,
                                            0.f,16384.f,20480.f,21504.f};

// scratch (device globals; allocation-free)
__device__ __align__(256) float   g_q   [NQ*DIM];
__device__ __align__(256) bf16    g_posf[NQ*DIM];
__device__ __align__(256) bf16    g_n   [NQ*DIM];
__device__ __align__(256) bf16    g_qin [NQ*DIM];
__device__ __align__(256) uint8_t g_val8[NQ*DIM];
__device__ __align__(256) bf16    g_oa  [NQ*384];
__device__ __align__(256) bf16    g_samp[NQ*DIM];
__device__ __align__(256) bf16    g_h1  [NQ*DFFN];
__device__ __align__(256) bf16    g_woa  [NLAY*384*256];
__device__ __align__(256) float   g_boa  [NLAY*384];
__device__ __align__(256) bf16    g_wval [NLAY*256*256];
__device__ __align__(256) bf16    g_wout [NLAY*256*256];
__device__ __align__(256) bf16    g_wg   [NLAY*2048*256];
__device__ __align__(256) float   g_bg   [NLAY*2048];
__device__ __align__(256) bf16    g_w2   [NLAY*256*DFFN];

// ---------------- PTX helpers --------------------------------------------
__device__ __forceinline__ uint32_t smem_u32(const void* p) {
    uint32_t a;
    asm("{ .reg .u64 t; cvta.to.shared.u64 t, %1; cvt.u32.u64 %0, t; }"
        : "=r"(a) : "l"(p));
    return a;
}
#define CPASYNC16(saddr, gptr) \
    asm volatile("cp.async.cg.shared.global [%0], [%1], 16;" \
                 :: "r"(saddr), "l"(gptr))
#define CPASYNC_COMMIT() asm volatile("cp.async.commit_group;" ::: "memory")
#define CPASYNC_WAIT(n)  asm volatile("cp.async.wait_group %0;" :: "n"(n) : "memory")
#define LDSM4(d0,d1,d2,d3,addr) \
    asm volatile("ldmatrix.sync.aligned.m8n8.x4.shared.b16 {%0,%1,%2,%3}, [%4];" \
                 : "=r"(d0),"=r"(d1),"=r"(d2),"=r"(d3) : "r"(addr))
#define MMA16816(c, a, b0, b1) \
    asm volatile("mma.sync.aligned.m16n8k16.row.col.f32.bf16.bf16.f32 " \
                 "{%0,%1,%2,%3},{%4,%5,%6,%7},{%8,%9},{%0,%1,%2,%3};" \
                 : "+f"((c)[0]),"+f"((c)[1]),"+f"((c)[2]),"+f"((c)[3]) \
                 : "r"((a)[0]),"r"((a)[1]),"r"((a)[2]),"r"((a)[3]), \
                   "r"(b0),"r"(b1))
#define SWZ128(off) ((off) ^ (((off) >> 3) & 0x70))

__device__ __forceinline__ uint32_t pack_bf2(float a, float b) {
    __nv_bfloat162 h = __floats2bfloat162_rn(a, b);
    return *reinterpret_cast<uint32_t*>(&h);
}
__device__ __forceinline__ uint16_t pk_e4m3(float lo, float hi) {
    uint16_t r;
    asm("cvt.rn.satfinite.e4m3x2.f32 %0, %1, %2;" : "=h"(r) : "f"(hi), "f"(lo));
    return r;
}
__device__ __forceinline__ __half2 e4h2(uint16_t u) {
    uint32_t h;
    asm("cvt.rn.f16x2.e4m3x2 %0, %1;" : "=r"(h) : "h"(u));
    return *reinterpret_cast<__half2*>(&h);
}
__device__ __forceinline__ __half2 u2h2(uint32_t u) {
    return *reinterpret_cast<__half2*>(&u);
}
__device__ __forceinline__ float2 bf2f(uint32_t u) {
    return __bfloat1622float2(*reinterpret_cast<__nv_bfloat162*>(&u));
}

#define VAL_SCALE   8.0f
#define VAL_DESCALE 0.125f

// ================= bf16 tensor-core GEMM (BM=128) ============================
// EPI 1: C[f32] += ls[n]*v            (in-place residual)
// EPI 4: GLU: h1[m, n/2] = silu(v_even)*v_odd (bf16, width Nc/2)
// EPI 5: merged: tiles 0-1 -> val fp8 x8; tiles 2-4 -> oa bf16
#define STAGE_BYTES 32768
#define SMEM_TOTAL_GEMM (3*STAGE_BYTES)

template<int EPI>
__global__ void __launch_bounds__(256, 2)
hgemm(int Nc, int K,
      const bf16* __restrict__ A, const bf16* __restrict__ B,
      const float* __restrict__ bias, void* __restrict__ Cv,
      const float* __restrict__ ls,
      const bf16* __restrict__ A2, const bf16* __restrict__ B2,
      const float* __restrict__ bias2, void* __restrict__ Cv2)
{
    extern __shared__ uint8_t dsm[];
    const uint32_t s0 = smem_u32(dsm);

    const int tid = threadIdx.x;
    const int lane = tid & 31, wid = tid >> 5;
    const int warp_m = wid >> 2, warp_n = wid & 3;
    const int bn = blockIdx.x, bm = blockIdx.y;
    const int NCH = K >> 6;

    const bf16* Ause = A;  const bf16* Buse = B;
    const float* biasuse = bias;
    void* Cuse = Cv;
    int NcU = Nc, bnl = bn;
    if (EPI == 5 && bn >= 2) {
        Ause = A2; Buse = B2; biasuse = bias2; Cuse = Cv2;
        NcU = 384; bnl = bn - 2;
    }

    const bf16* Ag = Ause + (size_t)(bm * 128) * K;
    const bf16* Bg = Buse + (size_t)(bnl * 128) * K;

    auto issue = [&](int c, int s) {
        uint32_t sa = s0 + s * STAGE_BYTES;
        uint32_t sb = sa + 16384;
        const bf16* Agp = Ag + c * 64;
        const bf16* Bgp = Bg + c * 64;
        #pragma unroll
        for (int j = 0; j < 4; j++) {
            int idx = tid + 256 * j;
            int row = idx >> 3, q = idx & 7;
            CPASYNC16(sa + SWZ128(row * 128 + q * 16),
                      Agp + (size_t)row * K + q * 8);
        }
        #pragma unroll
        for (int j = 0; j < 4; j++) {
            int idx = tid + 256 * j;
            int row = idx >> 3, q = idx & 7;
            CPASYNC16(sb + SWZ128(row * 128 + q * 16),
                      Bgp + (size_t)row * K + q * 8);
        }
        CPASYNC_COMMIT();
    };

    float acc[4][4][4];
    #pragma unroll
    for (int i = 0; i < 4; i++)
        #pragma unroll
        for (int j = 0; j < 4; j++)
            #pragma unroll
            for (int k = 0; k < 4; k++) acc[i][j][k] = 0.f;

    const int mat = lane >> 3, r8 = lane & 7;

    issue(0, 0);
    issue(1, 1);
    int s = 0;
    for (int c = 0; c < NCH; c++) {
        if (c + 1 < NCH) { CPASYNC_WAIT(1); } else { CPASYNC_WAIT(0); }
        __syncthreads();
        if (c + 2 < NCH) issue(c + 2, (s + 2) % 3);

        uint32_t sa = s0 + s * STAGE_BYTES;
        uint32_t sb = sa + 16384;
        #pragma unroll
        for (int ks = 0; ks < 4; ks++) {
            uint32_t a[4][4], bfr[4][2];
            #pragma unroll
            for (int mt = 0; mt < 4; mt++) {
                int row = warp_m * 64 + mt * 16 + (mat & 1) * 8 + r8;
                int kb  = ks * 32 + (mat >> 1) * 16;
                LDSM4(a[mt][0], a[mt][1], a[mt][2], a[mt][3],
                      sa + SWZ128(row * 128 + kb));
            }
            #pragma unroll
            for (int np = 0; np < 2; np++) {
                int nrow = warp_n * 32 + np * 16 + (mat >> 1) * 8 + r8;
                int kb   = ks * 32 + (mat & 1) * 16;
                uint32_t t0, t1, t2, t3;
                LDSM4(t0, t1, t2, t3, sb + SWZ128(nrow * 128 + kb));
                bfr[np*2+0][0] = t0; bfr[np*2+0][1] = t1;
                bfr[np*2+1][0] = t2; bfr[np*2+1][1] = t3;
            }
            #pragma unroll
            for (int mt = 0; mt < 4; mt++)
                #pragma unroll
                for (int nt = 0; nt < 4; nt++)
                    MMA16816(acc[mt][nt], a[mt], bfr[nt][0], bfr[nt][1]);
        }
        s = (s + 1) % 3;
    }

    const int g  = lane >> 2, tg = lane & 3;
    const int rbase = bm * 128 + warp_m * 64;
    const int cbase = bnl * 128 + warp_n * 32;

    #pragma unroll
    for (int mt = 0; mt < 4; mt++) {
        #pragma unroll
        for (int nt = 0; nt < 4; nt++) {
            int col = cbase + nt * 8 + tg * 2;
            float2 bs2 = *(const float2*)(biasuse + col);
            int r0 = rbase + mt * 16 + g;
            float v00 = acc[mt][nt][0] + bs2.x, v01 = acc[mt][nt][1] + bs2.y;
            float v10 = acc[mt][nt][2] + bs2.x, v11 = acc[mt][nt][3] + bs2.y;

            if (EPI == 4) {
                int j = col >> 1;
                int ncout = Nc >> 1;
                float g0 = (v00 / (1.f + __expf(-v00))) * v01;
                float g1 = (v10 / (1.f + __expf(-v10))) * v11;
                bf16* Cb = (bf16*)Cuse;
                Cb[(size_t)r0 * ncout + j]       = __float2bfloat16(g0);
                Cb[(size_t)(r0 + 8) * ncout + j] = __float2bfloat16(g1);
            } else {
                size_t i0 = (size_t)r0 * NcU + col;
                size_t i1 = (size_t)(r0 + 8) * NcU + col;
                if (EPI == 1) {
                    float2 ls2 = *(const float2*)(ls + col);
                    float* Cf = (float*)Cuse;
                    float2 q0 = *(float2*)(Cf + i0);
                    float2 q1 = *(float2*)(Cf + i1);
                    q0.x += ls2.x * v00; q0.y += ls2.y * v01;
                    q1.x += ls2.x * v10; q1.y += ls2.y * v11;
                    *(float2*)(Cf + i0) = q0;
                    *(float2*)(Cf + i1) = q1;
                } else if (EPI == 5 && bn < 2) {
                    uint8_t* Cb = (uint8_t*)Cuse;
                    *(uint16_t*)(Cb + i0) = pk_e4m3(v00 * VAL_SCALE, v01 * VAL_SCALE);
                    *(uint16_t*)(Cb + i1) = pk_e4m3(v10 * VAL_SCALE, v11 * VAL_SCALE);
                } else {
                    bf16* Cb = (bf16*)Cuse;
                    *(uint32_t*)(Cb + i0) = pack_bf2(v00, v01);
                    *(uint32_t*)(Cb + i1) = pack_bf2(v10, v11);
                }
            }
        }
    }
}

// ================= bf16 tensor-core GEMM (BM=64, w2 path) ====================
// EPI 1: C[f32] += ls[n]*v ; EPI 6: Cv2[f32] = Cv[f32] + ls[n]*v
// BM=64, BN=128, 3-stage; grid (Nc/128, M/64) -> better wave quantization.
#define STAGE64 24576
#define SMEM_TOTAL_G64 (3*STAGE64)

template<int EPI>
__global__ void __launch_bounds__(256, 2)
hgemm64(int Nc, int K,
        const bf16* __restrict__ A, const bf16* __restrict__ B,
        const float* __restrict__ bias, void* __restrict__ Cv,
        const float* __restrict__ ls, void* __restrict__ Cv2)
{
    extern __shared__ uint8_t dsm[];
    const uint32_t s0 = smem_u32(dsm);

    const int tid = threadIdx.x;
    const int lane = tid & 31, wid = tid >> 5;
    const int warp_m = wid >> 2, warp_n = wid & 3;   // 2 x 4
    const int bn = blockIdx.x, bm = blockIdx.y;
    const int NCH = K >> 6;

    const bf16* Ag = A + (size_t)(bm * 64) * K;
    const bf16* Bg = B + (size_t)(bn * 128) * K;

    auto issue = [&](int c, int s) {
        uint32_t sa = s0 + s * STAGE64;          // A: 64 rows x 128B = 8KB
        uint32_t sb = sa + 8192;                 // B: 128 rows x 128B = 16KB
        const bf16* Agp = Ag + c * 64;
        const bf16* Bgp = Bg + c * 64;
        #pragma unroll
        for (int j = 0; j < 2; j++) {
            int idx = tid + 256 * j;             // 0..511
            int row = idx >> 3, q = idx & 7;
            CPASYNC16(sa + SWZ128(row * 128 + q * 16),
                      Agp + (size_t)row * K + q * 8);
        }
        #pragma unroll
        for (int j = 0; j < 4; j++) {
            int idx = tid + 256 * j;
            int row = idx >> 3, q = idx & 7;
            CPASYNC16(sb + SWZ128(row * 128 + q * 16),
                      Bgp + (size_t)row * K + q * 8);
        }
        CPASYNC_COMMIT();
    };

    float acc[2][4][4];
    #pragma unroll
    for (int i = 0; i < 2; i++)
        #pragma unroll
        for (int j = 0; j < 4; j++)
            #pragma unroll
            for (int k = 0; k < 4; k++) acc[i][j][k] = 0.f;

    const int mat = lane >> 3, r8 = lane & 7;

    issue(0, 0);
    issue(1, 1);
    int s = 0;
    for (int c = 0; c < NCH; c++) {
        if (c + 1 < NCH) { CPASYNC_WAIT(1); } else { CPASYNC_WAIT(0); }
        __syncthreads();
        if (c + 2 < NCH) issue(c + 2, (s + 2) % 3);

        uint32_t sa = s0 + s * STAGE64;
        uint32_t sb = sa + 8192;
        #pragma unroll
        for (int ks = 0; ks < 4; ks++) {
            uint32_t a[2][4], bfr[4][2];
            #pragma unroll
            for (int mt = 0; mt < 2; mt++) {
                int row = warp_m * 32 + mt * 16 + (mat & 1) * 8 + r8;
                int kb  = ks * 32 + (mat >> 1) * 16;
                LDSM4(a[mt][0], a[mt][1], a[mt][2], a[mt][3],
                      sa + SWZ128(row * 128 + kb));
            }
            #pragma unroll
            for (int np = 0; np < 2; np++) {
                int nrow = warp_n * 32 + np * 16 + (mat >> 1) * 8 + r8;
                int kb   = ks * 32 + (mat & 1) * 16;
                uint32_t t0, t1, t2, t3;
                LDSM4(t0, t1, t2, t3, sb + SWZ128(nrow * 128 + kb));
                bfr[np*2+0][0] = t0; bfr[np*2+0][1] = t1;
                bfr[np*2+1][0] = t2; bfr[np*2+1][1] = t3;
            }
            #pragma unroll
            for (int mt = 0; mt < 2; mt++)
                #pragma unroll
                for (int nt = 0; nt < 4; nt++)
                    MMA16816(acc[mt][nt], a[mt], bfr[nt][0], bfr[nt][1]);
        }
        s = (s + 1) % 3;
    }

    const int g  = lane >> 2, tg = lane & 3;
    const int rbase = bm * 64 + warp_m * 32;
    const int cbase = bn * 128 + warp_n * 32;

    #pragma unroll
    for (int mt = 0; mt < 2; mt++) {
        #pragma unroll
        for (int nt = 0; nt < 4; nt++) {
            int col = cbase + nt * 8 + tg * 2;
            float2 bs2 = *(const float2*)(bias + col);
            float2 ls2 = *(const float2*)(ls + col);
            int r0 = rbase + mt * 16 + g;
            float v00 = acc[mt][nt][0] + bs2.x, v01 = acc[mt][nt][1] + bs2.y;
            float v10 = acc[mt][nt][2] + bs2.x, v11 = acc[mt][nt][3] + bs2.y;
            size_t i0 = (size_t)r0 * Nc + col;
            size_t i1 = (size_t)(r0 + 8) * Nc + col;
            if (EPI == 1) {
                float* Cf = (float*)Cv;
                float2 q0 = *(float2*)(Cf + i0);
                float2 q1 = *(float2*)(Cf + i1);
                q0.x += ls2.x * v00; q0.y += ls2.y * v01;
                q1.x += ls2.x * v10; q1.y += ls2.y * v11;
                *(float2*)(Cf + i0) = q0;
                *(float2*)(Cf + i1) = q1;
            } else {   // EPI 6
                const float* Qf = (const float*)Cv;
                float* Of = (float*)Cv2;
                float2 q0 = *(const float2*)(Qf + i0);
                float2 q1 = *(const float2*)(Qf + i1);
                q0.x += ls2.x * v00; q0.y += ls2.y * v01;
                q1.x += ls2.x * v10; q1.y += ls2.y * v11;
                *(float2*)(Of + i0) = q0;
                *(float2*)(Of + i1) = q1;
            }
        }
    }
}

// ---------------- transpose + weight prep + output tail (single launch) -----
struct Ptrs8 { const float* p[8]; };
struct PrepArgs {
    const float *Woff, *Wattn, *boff, *battn, *Wval, *Wout;
    const float *W1, *W3, *b1, *b3, *W2;
    bf16 *woa; float *boa; bf16 *wval, *wout, *wg; float *bg; bf16 *w2;
    float *out; int out_size;
};

__global__ void __launch_bounds__(256)
transpose_prep(Ptrs8 ps, const float* __restrict__ le,
               float* __restrict__ dq, bf16* __restrict__ dp, PrepArgs pa)
{
    __shared__ float tile[32][33];
    int p0 = blockIdx.x * 32;
    int d0 = blockIdx.y * 32;
    int bz = blockIdx.z;
    int b = bz >> 1, t = bz & 1;
    int tx = threadIdx.x, ty = threadIdx.y;

    int lvl = (p0 >= 21504) ? 3 : (p0 >= 20480) ? 2 : (p0 >= 16384) ? 1 : 0;
    int HW  = c_LW[lvl] * c_LW[lvl];
    int loc = p0 - c_LS[lvl];

    const float* s = ps.p[t * 4 + lvl] + ((size_t)b * DIM + d0) * HW + loc;
    #pragma unroll
    for (int i = ty; i < 32; i += 8)
        tile[i][tx] = s[(size_t)i * HW + tx];
    __syncthreads();
    #pragma unroll
    for (int i = ty; i < 32; i += 8) {
        float v = tile[tx][i];
        size_t di = ((size_t)b * NTOK + p0 + i) * DIM + d0 + tx;
        if (t) dp[di] = __float2bfloat16(v + le[lvl * DIM + d0 + tx]);
        else   dq[di] = v;
    }

    if (bz != 0) return;
    int t0 = (blockIdx.y * gridDim.x + blockIdx.x) * 256 + ty * 32 + tx;
    int stride = gridDim.x * gridDim.y * 256;

    for (int i = t0; i < pa.out_size - QOUT; i += stride)
        pa.out[QOUT + i] = (i < 12) ? c_tail[i] : 0.f;

    for (int i = t0; i < NLAY*384*256; i += stride) {
        int layer = i / (384*256);
        int rem = i - layer * 384*256;
        int r = rem >> 8, k = rem & 255;
        float v = (r < 256) ? pa.Woff[layer*65536 + r*256 + k]
                            : pa.Wattn[layer*32768 + (r-256)*256 + k];
        pa.woa[i] = __float2bfloat16(v);
    }
    for (int i = t0; i < NLAY*384; i += stride) {
        int layer = i / 384, r = i - layer * 384;
        pa.boa[i] = (r < 256) ? pa.boff[layer*256 + r]
                              : pa.battn[layer*128 + (r-256)];
    }
    for (int i = t0; i < NLAY*256*256; i += stride) {
        pa.wval[i] = __float2bfloat16(pa.Wval[i]);
        pa.wout[i] = __float2bfloat16(pa.Wout[i]);
    }
    for (int i = t0; i < NLAY*2048*256; i += stride) {
        int layer = i / (2048*256);
        int rem = i - layer * 2048*256;
        int r = rem >> 8, k = rem & 255;
        int j = r >> 1, sel = r & 1;
        const float* Wsrc = sel ? pa.W3 : pa.W1;
        pa.wg[i] = __float2bfloat16(Wsrc[(size_t)layer*DFFN*256 + j*256 + k]);
    }
    for (int i = t0; i < NLAY*2048; i += stride) {
        int layer = i / 2048, r = i - layer * 2048;
        int j = r >> 1, sel = r & 1;
        pa.bg[i] = sel ? pa.b3[layer*DFFN + j] : pa.b1[layer*DFFN + j];
    }
    for (int i = t0; i < NLAY*256*DFFN; i += stride)
        pa.w2[i] = __float2bfloat16(pa.W2[i]);
}

// ---------------- RMSNorm (fp32 q in, bf16 posf) -> bf16 n (+ bf16 qin) -----
__global__ void __launch_bounds__(256)
rms_kernel(const float* __restrict__ x, const float* __restrict__ g,
           const bf16* __restrict__ posf, bf16* __restrict__ out_n,
           bf16* __restrict__ out_qin)
{
    int warp = threadIdx.x >> 5, lane = threadIdx.x & 31;
    int row  = blockIdx.x * 8 + warp;
    const float* xr = x + (size_t)row * DIM;

    float4 v0 = *(const float4*)(xr + lane * 4);
    float4 v1 = *(const float4*)(xr + 128 + lane * 4);
    float s = v0.x*v0.x + v0.y*v0.y + v0.z*v0.z + v0.w*v0.w
            + v1.x*v1.x + v1.y*v1.y + v1.z*v1.z + v1.w*v1.w;
    #pragma unroll
    for (int o = 16; o; o >>= 1) s += __shfl_xor_sync(0xffffffffu, s, o);
    float scale = rsqrtf(s * (1.0f / 256.0f) + 1e-6f);

    float4 ga = *(const float4*)(g + lane * 4);
    float4 gb = *(const float4*)(g + 128 + lane * 4);
    float n0x = v0.x*scale*ga.x, n0y = v0.y*scale*ga.y;
    float n0z = v0.z*scale*ga.z, n0w = v0.w*scale*ga.w;
    float n1x = v1.x*scale*gb.x, n1y = v1.y*scale*gb.y;
    float n1z = v1.z*scale*gb.z, n1w = v1.w*scale*gb.w;

    bf16* nr = out_n + (size_t)row * DIM;
    *(uint2*)(nr + lane * 4)       = make_uint2(pack_bf2(n0x, n0y), pack_bf2(n0z, n0w));
    *(uint2*)(nr + 128 + lane * 4) = make_uint2(pack_bf2(n1x, n1y), pack_bf2(n1z, n1w));

    if (out_qin) {
        const bf16* pr = posf + (size_t)row * DIM;
        uint2 pa2 = *(const uint2*)(pr + lane * 4);
        uint2 pb2 = *(const uint2*)(pr + 128 + lane * 4);
        float2 p0 = bf2f(pa2.x), p1 = bf2f(pa2.y);
        float2 p2 = bf2f(pb2.x), p3 = bf2f(pb2.y);
        bf16* qr = out_qin + (size_t)row * DIM;
        *(uint2*)(qr + lane * 4) =
            make_uint2(pack_bf2(n0x + p0.x, n0y + p0.y), pack_bf2(n0z + p1.x, n0w + p1.y));
        *(uint2*)(qr + 128 + lane * 4) =
            make_uint2(pack_bf2(n1x + p2.x, n1y + p2.y), pack_bf2(n1z + p3.x, n1w + p3.y));
    }
}

// ---------------- deformable sampling: 2 tokens/block, 2-phase ---------------
__global__ void __launch_bounds__(256)
msda_kernel(const bf16* __restrict__ oa, const uint8_t* __restrict__ value,
            bf16* __restrict__ samp)
{
    __shared__ __align__(16) uint32_t s_off[256][4];
    __shared__ __align__(16) uint32_t s_w  [256][4];

    int row0 = blockIdx.x * 2;
    int tid = threadIdx.x;

    {
        int tok = tid >> 7, tt = tid & 127;
        int row = row0 + tok;
        int b = row / NTOK;
        int n = row - b * NTOK;
        int h = tt >> 4, p = tt & 15;

        float lg = __bfloat162float(oa[(size_t)row * 384 + 256 + h * 16 + p]);
        float mx = lg;
        #pragma unroll
        for (int o = 8; o; o >>= 1)
            mx = fmaxf(mx, __shfl_xor_sync(0xffffffffu, mx, o));
        float e = __expf(lg - mx);
        float ssum = e;
        #pragma unroll
        for (int o = 8; o; o >>= 1)
            ssum += __shfl_xor_sync(0xffffffffu, ssum, o);
        float aw = e / ssum;

        int lvq = (n >= 21504) ? 3 : (n >= 20480) ? 2 : (n >= 16384) ? 1 : 0;
        int Wq  = c_LW[lvq];
        int li  = n - c_LS[lvq];
        int iy  = li / Wq, ix = li - iy * Wq;
        float refx = (ix + 0.5f) / (float)Wq;
        float refy = (iy + 0.5f) / (float)Wq;

        int l  = p >> 2;
        int Wl = c_LW[l], st = c_LS[l];
        float fW = (float)Wl;
        float2 o2 = __bfloat1622float2(
            *(const __nv_bfloat162*)(oa + (size_t)row * 384 + h * 32 + p * 2));
        float xx = (refx + o2.x / fW) * fW - 0.5f;
        float yy = (refy + o2.y / fW) * fW - 0.5f;
        float x0f = floorf(xx), y0f = floorf(yy);
        int x0 = (int)x0f, y0 = (int)y0f;
        float fx = xx - x0f, fy = yy - y0f;
        float wx0 = (x0 >= 0     && x0 < Wl)     ? (1.f - fx) : 0.f;
        float wx1 = (x0 + 1 >= 0 && x0 + 1 < Wl) ? fx         : 0.f;
        float wy0 = (y0 >= 0     && y0 < Wl)     ? (1.f - fy) * aw : 0.f;
        float wy1 = (y0 + 1 >= 0 && y0 + 1 < Wl) ? fy * aw        : 0.f;
        int x0c = min(max(x0, 0), Wl - 1);
        int x1c = min(max(x0 + 1, 0), Wl - 1);
        int y0c = min(max(y0, 0), Wl - 1);
        int y1c = min(max(y0 + 1, 0), Wl - 1);
        int r0i = st + y0c * Wl, r1i = st + y1c * Wl;
        s_off[tid][0] = (uint32_t)(r0i + x0c) << 8;
        s_off[tid][1] = (uint32_t)(r0i + x1c) << 8;
        s_off[tid][2] = (uint32_t)(r1i + x0c) << 8;
        s_off[tid][3] = (uint32_t)(r1i + x1c) << 8;
        __half2 w0 = __floats2half2_rn(wx0 * wy0, wx0 * wy0);
        __half2 w1 = __floats2half2_rn(wx1 * wy0, wx1 * wy0);
        __half2 w2 = __floats2half2_rn(wx0 * wy1, wx0 * wy1);
        __half2 w3 = __floats2half2_rn(wx1 * wy1, wx1 * wy1);
        s_w[tid][0] = *reinterpret_cast<uint32_t*>(&w0);
        s_w[tid][1] = *reinterpret_cast<uint32_t*>(&w1);
        s_w[tid][2] = *reinterpret_cast<uint32_t*>(&w2);
        s_w[tid][3] = *reinterpret_cast<uint32_t*>(&w3);
    }
    __syncthreads();

    int h    = tid >> 5;
    int lane = tid & 31;
    int ch   = lane & 15;
    int half = lane >> 4;

    #pragma unroll
    for (int tok = 0; tok < 2; tok++) {
        int row = row0 + tok;
        int b = row / NTOK;
        const uint8_t* vb = value + ((size_t)b * NTOK) * 256 + h * 32 + ch * 2;

        __half2 acc = __floats2half2_rn(0.f, 0.f);
        #pragma unroll
        for (int j = 0; j < 8; j++) {
            int e = tok * 128 + h * 16 + j * 2 + half;
            uint4 off = *(const uint4*)(&s_off[e][0]);
            uint4 ww  = *(const uint4*)(&s_w[e][0]);
            __half2 f0 = e4h2(*(const uint16_t*)(vb + off.x));
            __half2 f1 = e4h2(*(const uint16_t*)(vb + off.y));
            __half2 f2 = e4h2(*(const uint16_t*)(vb + off.z));
            __half2 f3 = e4h2(*(const uint16_t*)(vb + off.w));
            acc = __hfma2(u2h2(ww.x), f0, acc);
            acc = __hfma2(u2h2(ww.y), f1, acc);
            acc = __hfma2(u2h2(ww.z), f2, acc);
            acc = __hfma2(u2h2(ww.w), f3, acc);
        }
        float2 a = __half22float2(acc);
        a.x += __shfl_xor_sync(0xffffffffu, a.x, 16);
        a.y += __shfl_xor_sync(0xffffffffu, a.y, 16);
        if (half == 0) {
            uint32_t* sp = (uint32_t*)(samp + (size_t)row * 256 + h * 32);
            sp[ch] = pack_bf2(a.x * VAL_DESCALE, a.y * VAL_DESCALE);
        }
    }
}

// =============================== launcher ====================================
extern "C" void kernel_launch(void* const* d_in, const int* in_sizes, int n_in,
                              void* d_out, int out_size)
{
    (void)n_in;
    const float* src[4];
    const float* pos[4];
    bool interleaved = (in_sizes[1] == in_sizes[0]);
    for (int i = 0; i < 4; i++) {
        if (interleaved) { src[i] = (const float*)d_in[2*i];
                           pos[i] = (const float*)d_in[2*i+1]; }
        else             { src[i] = (const float*)d_in[i];
                           pos[i] = (const float*)d_in[4+i]; }
    }
    const float* level_embed = (const float*)d_in[8];
    const float* W_off  = (const float*)d_in[9];
    const float* b_off  = (const float*)d_in[10];
    const float* W_attn = (const float*)d_in[11];
    const float* b_attn = (const float*)d_in[12];
    const float* W_val  = (const float*)d_in[13];
    const float* b_val  = (const float*)d_in[14];
    const float* W_out  = (const float*)d_in[15];
    const float* b_out  = (const float*)d_in[16];
    const float* g_na   = (const float*)d_in[17];
    const float* g_nf   = (const float*)d_in[18];
    const float* ls_a   = (const float*)d_in[19];
    const float* ls_f   = (const float*)d_in[20];
    const float* W1     = (const float*)d_in[21];
    const float* b1     = (const float*)d_in[22];
    const float* W3     = (const float*)d_in[23];
    const float* b3     = (const float*)d_in[24];
    const float* W2     = (const float*)d_in[25];
    const float* b2     = (const float*)d_in[26];

    float *q, *boa, *bg;
    bf16 *posf, *nbuf, *qin, *oab, *sampb, *h1;
    uint8_t *val8;
    bf16 *woa, *wval, *wout, *wg, *w2;
    cudaGetSymbolAddress((void**)&q,     g_q);
    cudaGetSymbolAddress((void**)&posf,  g_posf);
    cudaGetSymbolAddress((void**)&nbuf,  g_n);
    cudaGetSymbolAddress((void**)&qin,   g_qin);
    cudaGetSymbolAddress((void**)&val8,  g_val8);
    cudaGetSymbolAddress((void**)&oab,   g_oa);
    cudaGetSymbolAddress((void**)&sampb, g_samp);
    cudaGetSymbolAddress((void**)&h1,    g_h1);
    cudaGetSymbolAddress((void**)&woa,   g_woa);
    cudaGetSymbolAddress((void**)&boa,   g_boa);
    cudaGetSymbolAddress((void**)&wval,  g_wval);
    cudaGetSymbolAddress((void**)&wout,  g_wout);
    cudaGetSymbolAddress((void**)&wg,    g_wg);
    cudaGetSymbolAddress((void**)&bg,    g_bg);
    cudaGetSymbolAddress((void**)&w2,    g_w2);

    cudaFuncSetAttribute((const void*)hgemm<1>,   cudaFuncAttributeMaxDynamicSharedMemorySize, SMEM_TOTAL_GEMM);
    cudaFuncSetAttribute((const void*)hgemm<4>,   cudaFuncAttributeMaxDynamicSharedMemorySize, SMEM_TOTAL_GEMM);
    cudaFuncSetAttribute((const void*)hgemm<5>,   cudaFuncAttributeMaxDynamicSharedMemorySize, SMEM_TOTAL_GEMM);
    cudaFuncSetAttribute((const void*)hgemm64<1>, cudaFuncAttributeMaxDynamicSharedMemorySize, SMEM_TOTAL_G64);
    cudaFuncSetAttribute((const void*)hgemm64<6>, cudaFuncAttributeMaxDynamicSharedMemorySize, SMEM_TOTAL_G64);

    Ptrs8 ps;
    for (int l = 0; l < 4; l++) { ps.p[l] = src[l]; ps.p[4 + l] = pos[l]; }
    PrepArgs pa = { W_off, W_attn, b_off, b_attn, W_val, W_out,
                    W1, W3, b1, b3, W2,
                    woa, boa, wval, wout, wg, bg, w2,
                    (float*)d_out, out_size };

    const int MT = NQ / 128;
    dim3 g2(2, MT), g5(5, MT), g16(16, MT), g64(2, NQ / 64);
    const int SB = SMEM_TOTAL_GEMM, SB64 = SMEM_TOTAL_G64;

    transpose_prep<<<dim3(NTOK / 32, DIM / 32, BATCH * 2), dim3(32, 8)>>>(
        ps, level_embed, q, posf, pa);

    for (int i = 0; i < NLAY; i++) {
        rms_kernel<<<NQ / 8, 256>>>(q, g_na + i * DIM, posf, nbuf, qin);
        hgemm<5><<<g5, 256, SB>>>(256, 256,
            nbuf, wval + (size_t)i*65536, b_val + i*256, val8, nullptr,
            qin,  woa  + (size_t)i*98304, boa + i*384, oab);
        msda_kernel<<<NQ / 2, 256>>>(oab, val8, sampb);
        hgemm<1><<<g2, 256, SB>>>(256, 256, sampb, wout + (size_t)i*65536,
                                  b_out + i*256, q, ls_a + i*256,
                                  nullptr, nullptr, nullptr, nullptr);
        rms_kernel<<<NQ / 8, 256>>>(q, g_nf + i * DIM, nullptr, nbuf, nullptr);
        hgemm<4><<<g16, 256, SB>>>(2048, 256, nbuf, wg + (size_t)i*524288,
                                   bg + i*2048, h1, nullptr,
                                   nullptr, nullptr, nullptr, nullptr);
        if (i < NLAY - 1) {
            hgemm64<1><<<g64, 256, SB64>>>(256, DFFN, h1, w2 + (size_t)i*262144,
                                           b2 + i*256, q, ls_f + i*256, nullptr);
        } else {
            hgemm64<6><<<g64, 256, SB64>>>(256, DFFN, h1, w2 + (size_t)i*262144,
                                           b2 + i*256, q, ls_f + i*256,
                                           (float*)d_out);
        }
    }
}

// round 16
// speedup vs baseline: 1.0103x; 1.0103x over previous
#include <cuda_runtime.h>
#include <cuda_bf16.h>
#include <cuda_fp16.h>
#include <cstdint>
#include <math.h>

#define NTOK   21760
#define BATCH  2
#define NQ     (NTOK*BATCH)
#define DIM    256
#define NLAY   6
#define DFFN   1024
#define QOUT   (NQ*DIM)

typedef __nv_bfloat16 bf16;

__device__ __constant__ int c_LW[4] = {128, 64, 32, 16};
__device__ __constant__ int c_LS[4] = {0, 16384, 20480, 21504};
__device__ __constant__ float c_tail[12] = {128.f,128.f,64.f,64.f,32.f,32.f,16.f,16.f,
                                            0.f,16384.f,20480.f,21504.f};

// scratch (device globals; allocation-free)
__device__ __align__(256) float   g_q   [NQ*DIM];
__device__ __align__(256) bf16    g_posf[NQ*DIM];
__device__ __align__(256) bf16    g_n   [NQ*DIM];
__device__ __align__(256) bf16    g_qin [NQ*DIM];
__device__ __align__(256) uint8_t g_val8[NQ*DIM];
__device__ __align__(256) bf16    g_oa  [NQ*384];
__device__ __align__(256) bf16    g_samp[NQ*DIM];
__device__ __align__(256) bf16    g_h1  [NQ*DFFN];
__device__ __align__(256) bf16    g_woa  [NLAY*384*256];
__device__ __align__(256) float   g_boa  [NLAY*384];
__device__ __align__(256) bf16    g_wval [NLAY*256*256];
__device__ __align__(256) bf16    g_wout [NLAY*256*256];
__device__ __align__(256) bf16    g_wg   [NLAY*2048*256];
__device__ __align__(256) float   g_bg   [NLAY*2048];
__device__ __align__(256) bf16    g_w2   [NLAY*256*DFFN];

// ---------------- PTX helpers --------------------------------------------
__device__ __forceinline__ uint32_t smem_u32(const void* p) {
    uint32_t a;
    asm("{ .reg .u64 t; cvta.to.shared.u64 t, %1; cvt.u32.u64 %0, t; }"
        : "=r"(a) : "l"(p));
    return a;
}
#define CPASYNC16(saddr, gptr) \
    asm volatile("cp.async.cg.shared.global [%0], [%1], 16;" \
                 :: "r"(saddr), "l"(gptr))
#define CPASYNC_COMMIT() asm volatile("cp.async.commit_group;" ::: "memory")
#define CPASYNC_WAIT(n)  asm volatile("cp.async.wait_group %0;" :: "n"(n) : "memory")
#define LDSM4(d0,d1,d2,d3,addr) \
    asm volatile("ldmatrix.sync.aligned.m8n8.x4.shared.b16 {%0,%1,%2,%3}, [%4];" \
                 : "=r"(d0),"=r"(d1),"=r"(d2),"=r"(d3) : "r"(addr))
#define MMA16816(c, a, b0, b1) \
    asm volatile("mma.sync.aligned.m16n8k16.row.col.f32.bf16.bf16.f32 " \
                 "{%0,%1,%2,%3},{%4,%5,%6,%7},{%8,%9},{%0,%1,%2,%3};" \
                 : "+f"((c)[0]),"+f"((c)[1]),"+f"((c)[2]),"+f"((c)[3]) \
                 : "r"((a)[0]),"r"((a)[1]),"r"((a)[2]),"r"((a)[3]), \
                   "r"(b0),"r"(b1))
#define SWZ128(off) ((off) ^ (((off) >> 3) & 0x70))

__device__ __forceinline__ uint32_t pack_bf2(float a, float b) {
    __nv_bfloat162 h = __floats2bfloat162_rn(a, b);
    return *reinterpret_cast<uint32_t*>(&h);
}
__device__ __forceinline__ uint16_t pk_e4m3(float lo, float hi) {
    uint16_t r;
    asm("cvt.rn.satfinite.e4m3x2.f32 %0, %1, %2;" : "=h"(r) : "f"(hi), "f"(lo));
    return r;
}
__device__ __forceinline__ __half2 e4h2(uint16_t u) {
    uint32_t h;
    asm("cvt.rn.f16x2.e4m3x2 %0, %1;" : "=r"(h) : "h"(u));
    return *reinterpret_cast<__half2*>(&h);
}
__device__ __forceinline__ __half2 u2h2(uint32_t u) {
    return *reinterpret_cast<__half2*>(&u);
}
__device__ __forceinline__ float2 bf2f(uint32_t u) {
    return __bfloat1622float2(*reinterpret_cast<__nv_bfloat162*>(&u));
}

#define VAL_SCALE   8.0f
#define VAL_DESCALE 0.125f

// ================= bf16 tensor-core GEMM =====================================
// EPI 1: C[f32] += ls[n]*v            (in-place residual)
// EPI 4: GLU: h1[m, n/2] = silu(v_even)*v_odd (bf16, width Nc/2)
// EPI 5: merged: tiles 0-1 -> val fp8 x8; tiles 2-4 -> oa bf16
// EPI 6: final: Cv2[f32] = Cv[f32] + ls[n]*v  (writes d_out only)
#define STAGE_BYTES 32768
#define SMEM_TOTAL_GEMM (3*STAGE_BYTES)

template<int EPI>
__global__ void __launch_bounds__(256, 2)
hgemm(int Nc, int K,
      const bf16* __restrict__ A, const bf16* __restrict__ B,
      const float* __restrict__ bias, void* __restrict__ Cv,
      const float* __restrict__ ls,
      const bf16* __restrict__ A2, const bf16* __restrict__ B2,
      const float* __restrict__ bias2, void* __restrict__ Cv2)
{
    extern __shared__ uint8_t dsm[];
    const uint32_t s0 = smem_u32(dsm);

    const int tid = threadIdx.x;
    const int lane = tid & 31, wid = tid >> 5;
    const int warp_m = wid >> 2, warp_n = wid & 3;
    const int bn = blockIdx.x, bm = blockIdx.y;
    const int NCH = K >> 6;

    const bf16* Ause = A;  const bf16* Buse = B;
    const float* biasuse = bias;
    void* Cuse = Cv;
    int NcU = Nc, bnl = bn;
    if (EPI == 5 && bn >= 2) {
        Ause = A2; Buse = B2; biasuse = bias2; Cuse = Cv2;
        NcU = 384; bnl = bn - 2;
    }

    const bf16* Ag = Ause + (size_t)(bm * 128) * K;
    const bf16* Bg = Buse + (size_t)(bnl * 128) * K;

    auto issue = [&](int c, int s) {
        uint32_t sa = s0 + s * STAGE_BYTES;
        uint32_t sb = sa + 16384;
        const bf16* Agp = Ag + c * 64;
        const bf16* Bgp = Bg + c * 64;
        #pragma unroll
        for (int j = 0; j < 4; j++) {
            int idx = tid + 256 * j;
            int row = idx >> 3, q = idx & 7;
            CPASYNC16(sa + SWZ128(row * 128 + q * 16),
                      Agp + (size_t)row * K + q * 8);
        }
        #pragma unroll
        for (int j = 0; j < 4; j++) {
            int idx = tid + 256 * j;
            int row = idx >> 3, q = idx & 7;
            CPASYNC16(sb + SWZ128(row * 128 + q * 16),
                      Bgp + (size_t)row * K + q * 8);
        }
        CPASYNC_COMMIT();
    };

    float acc[4][4][4];
    #pragma unroll
    for (int i = 0; i < 4; i++)
        #pragma unroll
        for (int j = 0; j < 4; j++)
            #pragma unroll
            for (int k = 0; k < 4; k++) acc[i][j][k] = 0.f;

    const int mat = lane >> 3, r8 = lane & 7;

    issue(0, 0);
    issue(1, 1);
    int s = 0;
    for (int c = 0; c < NCH; c++) {
        if (c + 1 < NCH) { CPASYNC_WAIT(1); } else { CPASYNC_WAIT(0); }
        __syncthreads();
        if (c + 2 < NCH) issue(c + 2, (s + 2) % 3);

        uint32_t sa = s0 + s * STAGE_BYTES;
        uint32_t sb = sa + 16384;
        #pragma unroll
        for (int ks = 0; ks < 4; ks++) {
            uint32_t a[4][4], bfr[4][2];
            #pragma unroll
            for (int mt = 0; mt < 4; mt++) {
                int row = warp_m * 64 + mt * 16 + (mat & 1) * 8 + r8;
                int kb  = ks * 32 + (mat >> 1) * 16;
                LDSM4(a[mt][0], a[mt][1], a[mt][2], a[mt][3],
                      sa + SWZ128(row * 128 + kb));
            }
            #pragma unroll
            for (int np = 0; np < 2; np++) {
                int nrow = warp_n * 32 + np * 16 + (mat >> 1) * 8 + r8;
                int kb   = ks * 32 + (mat & 1) * 16;
                uint32_t t0, t1, t2, t3;
                LDSM4(t0, t1, t2, t3, sb + SWZ128(nrow * 128 + kb));
                bfr[np*2+0][0] = t0; bfr[np*2+0][1] = t1;
                bfr[np*2+1][0] = t2; bfr[np*2+1][1] = t3;
            }
            #pragma unroll
            for (int mt = 0; mt < 4; mt++)
                #pragma unroll
                for (int nt = 0; nt < 4; nt++)
                    MMA16816(acc[mt][nt], a[mt], bfr[nt][0], bfr[nt][1]);
        }
        s = (s + 1) % 3;
    }

    const int g  = lane >> 2, tg = lane & 3;
    const int rbase = bm * 128 + warp_m * 64;
    const int cbase = bnl * 128 + warp_n * 32;

    #pragma unroll
    for (int mt = 0; mt < 4; mt++) {
        #pragma unroll
        for (int nt = 0; nt < 4; nt++) {
            int col = cbase + nt * 8 + tg * 2;
            float2 bs2 = *(const float2*)(biasuse + col);
            int r0 = rbase + mt * 16 + g;
            float v00 = acc[mt][nt][0] + bs2.x, v01 = acc[mt][nt][1] + bs2.y;
            float v10 = acc[mt][nt][2] + bs2.x, v11 = acc[mt][nt][3] + bs2.y;

            if (EPI == 4) {
                int j = col >> 1;
                int ncout = Nc >> 1;
                float g0 = (v00 / (1.f + __expf(-v00))) * v01;
                float g1 = (v10 / (1.f + __expf(-v10))) * v11;
                bf16* Cb = (bf16*)Cuse;
                Cb[(size_t)r0 * ncout + j]       = __float2bfloat16(g0);
                Cb[(size_t)(r0 + 8) * ncout + j] = __float2bfloat16(g1);
            } else {
                size_t i0 = (size_t)r0 * NcU + col;
                size_t i1 = (size_t)(r0 + 8) * NcU + col;
                if (EPI == 1) {
                    float2 ls2 = *(const float2*)(ls + col);
                    float* Cf = (float*)Cuse;
                    float2 q0 = *(float2*)(Cf + i0);
                    float2 q1 = *(float2*)(Cf + i1);
                    q0.x += ls2.x * v00; q0.y += ls2.y * v01;
                    q1.x += ls2.x * v10; q1.y += ls2.y * v11;
                    *(float2*)(Cf + i0) = q0;
                    *(float2*)(Cf + i1) = q1;
                } else if (EPI == 6) {
                    float2 ls2 = *(const float2*)(ls + col);
                    const float* Qf = (const float*)Cuse;
                    float* Of = (float*)Cv2;
                    float2 q0 = *(const float2*)(Qf + i0);
                    float2 q1 = *(const float2*)(Qf + i1);
                    q0.x += ls2.x * v00; q0.y += ls2.y * v01;
                    q1.x += ls2.x * v10; q1.y += ls2.y * v11;
                    *(float2*)(Of + i0) = q0;
                    *(float2*)(Of + i1) = q1;
                } else if (EPI == 5 && bn < 2) {
                    uint8_t* Cb = (uint8_t*)Cuse;
                    *(uint16_t*)(Cb + i0) = pk_e4m3(v00 * VAL_SCALE, v01 * VAL_SCALE);
                    *(uint16_t*)(Cb + i1) = pk_e4m3(v10 * VAL_SCALE, v11 * VAL_SCALE);
                } else {
                    bf16* Cb = (bf16*)Cuse;
                    *(uint32_t*)(Cb + i0) = pack_bf2(v00, v01);
                    *(uint32_t*)(Cb + i1) = pack_bf2(v10, v11);
                }
            }
        }
    }
}

// ---------------- transpose + weight prep + output tail (single launch) -----
struct Ptrs8 { const float* p[8]; };
struct PrepArgs {
    const float *Woff, *Wattn, *boff, *battn, *Wval, *Wout;
    const float *W1, *W3, *b1, *b3, *W2;
    bf16 *woa; float *boa; bf16 *wval, *wout, *wg; float *bg; bf16 *w2;
    float *out; int out_size;
};

__global__ void __launch_bounds__(256)
transpose_prep(Ptrs8 ps, const float* __restrict__ le,
               float* __restrict__ dq, bf16* __restrict__ dp, PrepArgs pa)
{
    __shared__ float tile[32][33];
    int p0 = blockIdx.x * 32;
    int d0 = blockIdx.y * 32;
    int bz = blockIdx.z;
    int b = bz >> 1, t = bz & 1;
    int tx = threadIdx.x, ty = threadIdx.y;

    int lvl = (p0 >= 21504) ? 3 : (p0 >= 20480) ? 2 : (p0 >= 16384) ? 1 : 0;
    int HW  = c_LW[lvl] * c_LW[lvl];
    int loc = p0 - c_LS[lvl];

    const float* s = ps.p[t * 4 + lvl] + ((size_t)b * DIM + d0) * HW + loc;
    #pragma unroll
    for (int i = ty; i < 32; i += 8)
        tile[i][tx] = s[(size_t)i * HW + tx];
    __syncthreads();
    #pragma unroll
    for (int i = ty; i < 32; i += 8) {
        float v = tile[tx][i];
        size_t di = ((size_t)b * NTOK + p0 + i) * DIM + d0 + tx;
        if (t) dp[di] = __float2bfloat16(v + le[lvl * DIM + d0 + tx]);
        else   dq[di] = v;
    }

    if (bz != 0) return;
    int t0 = (blockIdx.y * gridDim.x + blockIdx.x) * 256 + ty * 32 + tx;
    int stride = gridDim.x * gridDim.y * 256;

    for (int i = t0; i < pa.out_size - QOUT; i += stride)
        pa.out[QOUT + i] = (i < 12) ? c_tail[i] : 0.f;

    for (int i = t0; i < NLAY*384*256; i += stride) {
        int layer = i / (384*256);
        int rem = i - layer * 384*256;
        int r = rem >> 8, k = rem & 255;
        float v = (r < 256) ? pa.Woff[layer*65536 + r*256 + k]
                            : pa.Wattn[layer*32768 + (r-256)*256 + k];
        pa.woa[i] = __float2bfloat16(v);
    }
    for (int i = t0; i < NLAY*384; i += stride) {
        int layer = i / 384, r = i - layer * 384;
        pa.boa[i] = (r < 256) ? pa.boff[layer*256 + r]
                              : pa.battn[layer*128 + (r-256)];
    }
    for (int i = t0; i < NLAY*256*256; i += stride) {
        pa.wval[i] = __float2bfloat16(pa.Wval[i]);
        pa.wout[i] = __float2bfloat16(pa.Wout[i]);
    }
    for (int i = t0; i < NLAY*2048*256; i += stride) {
        int layer = i / (2048*256);
        int rem = i - layer * 2048*256;
        int r = rem >> 8, k = rem & 255;
        int j = r >> 1, sel = r & 1;
        const float* Wsrc = sel ? pa.W3 : pa.W1;
        pa.wg[i] = __float2bfloat16(Wsrc[(size_t)layer*DFFN*256 + j*256 + k]);
    }
    for (int i = t0; i < NLAY*2048; i += stride) {
        int layer = i / 2048, r = i - layer * 2048;
        int j = r >> 1, sel = r & 1;
        pa.bg[i] = sel ? pa.b3[layer*DFFN + j] : pa.b1[layer*DFFN + j];
    }
    for (int i = t0; i < NLAY*256*DFFN; i += stride)
        pa.w2[i] = __float2bfloat16(pa.W2[i]);
}

// ---------------- RMSNorm (fp32 q in, bf16 posf) -> bf16 n (+ bf16 qin) -----
__global__ void __launch_bounds__(256)
rms_kernel(const float* __restrict__ x, const float* __restrict__ g,
           const bf16* __restrict__ posf, bf16* __restrict__ out_n,
           bf16* __restrict__ out_qin)
{
    int warp = threadIdx.x >> 5, lane = threadIdx.x & 31;
    int row  = blockIdx.x * 8 + warp;
    const float* xr = x + (size_t)row * DIM;

    float4 v0 = *(const float4*)(xr + lane * 4);
    float4 v1 = *(const float4*)(xr + 128 + lane * 4);
    float s = v0.x*v0.x + v0.y*v0.y + v0.z*v0.z + v0.w*v0.w
            + v1.x*v1.x + v1.y*v1.y + v1.z*v1.z + v1.w*v1.w;
    #pragma unroll
    for (int o = 16; o; o >>= 1) s += __shfl_xor_sync(0xffffffffu, s, o);
    float scale = rsqrtf(s * (1.0f / 256.0f) + 1e-6f);

    float4 ga = *(const float4*)(g + lane * 4);
    float4 gb = *(const float4*)(g + 128 + lane * 4);
    float n0x = v0.x*scale*ga.x, n0y = v0.y*scale*ga.y;
    float n0z = v0.z*scale*ga.z, n0w = v0.w*scale*ga.w;
    float n1x = v1.x*scale*gb.x, n1y = v1.y*scale*gb.y;
    float n1z = v1.z*scale*gb.z, n1w = v1.w*scale*gb.w;

    bf16* nr = out_n + (size_t)row * DIM;
    *(uint2*)(nr + lane * 4)       = make_uint2(pack_bf2(n0x, n0y), pack_bf2(n0z, n0w));
    *(uint2*)(nr + 128 + lane * 4) = make_uint2(pack_bf2(n1x, n1y), pack_bf2(n1z, n1w));

    if (out_qin) {
        const bf16* pr = posf + (size_t)row * DIM;
        uint2 pa2 = *(const uint2*)(pr + lane * 4);
        uint2 pb2 = *(const uint2*)(pr + 128 + lane * 4);
        float2 p0 = bf2f(pa2.x), p1 = bf2f(pa2.y);
        float2 p2 = bf2f(pb2.x), p3 = bf2f(pb2.y);
        bf16* qr = out_qin + (size_t)row * DIM;
        *(uint2*)(qr + lane * 4) =
            make_uint2(pack_bf2(n0x + p0.x, n0y + p0.y), pack_bf2(n0z + p1.x, n0w + p1.y));
        *(uint2*)(qr + 128 + lane * 4) =
            make_uint2(pack_bf2(n1x + p2.x, n1y + p2.y), pack_bf2(n1z + p3.x, n1w + p3.y));
    }
}

// ---------------- deformable sampling: 2 tokens/block, 2-phase ---------------
__global__ void __launch_bounds__(256)
msda_kernel(const bf16* __restrict__ oa, const uint8_t* __restrict__ value,
            bf16* __restrict__ samp)
{
    __shared__ __align__(16) uint32_t s_off[256][4];
    __shared__ __align__(16) uint32_t s_w  [256][4];

    int row0 = blockIdx.x * 2;
    int tid = threadIdx.x;

    {
        int tok = tid >> 7, tt = tid & 127;
        int row = row0 + tok;
        int b = row / NTOK;
        int n = row - b * NTOK;
        int h = tt >> 4, p = tt & 15;

        float lg = __bfloat162float(oa[(size_t)row * 384 + 256 + h * 16 + p]);
        float mx = lg;
        #pragma unroll
        for (int o = 8; o; o >>= 1)
            mx = fmaxf(mx, __shfl_xor_sync(0xffffffffu, mx, o));
        float e = __expf(lg - mx);
        float ssum = e;
        #pragma unroll
        for (int o = 8; o; o >>= 1)
            ssum += __shfl_xor_sync(0xffffffffu, ssum, o);
        float aw = e / ssum;

        int lvq = (n >= 21504) ? 3 : (n >= 20480) ? 2 : (n >= 16384) ? 1 : 0;
        int Wq  = c_LW[lvq];
        int li  = n - c_LS[lvq];
        int iy  = li / Wq, ix = li - iy * Wq;
        float refx = (ix + 0.5f) / (float)Wq;
        float refy = (iy + 0.5f) / (float)Wq;

        int l  = p >> 2;
        int Wl = c_LW[l], st = c_LS[l];
        float fW = (float)Wl;
        float2 o2 = __bfloat1622float2(
            *(const __nv_bfloat162*)(oa + (size_t)row * 384 + h * 32 + p * 2));
        float xx = (refx + o2.x / fW) * fW - 0.5f;
        float yy = (refy + o2.y / fW) * fW - 0.5f;
        float x0f = floorf(xx), y0f = floorf(yy);
        int x0 = (int)x0f, y0 = (int)y0f;
        float fx = xx - x0f, fy = yy - y0f;
        float wx0 = (x0 >= 0     && x0 < Wl)     ? (1.f - fx) : 0.f;
        float wx1 = (x0 + 1 >= 0 && x0 + 1 < Wl) ? fx         : 0.f;
        float wy0 = (y0 >= 0     && y0 < Wl)     ? (1.f - fy) * aw : 0.f;
        float wy1 = (y0 + 1 >= 0 && y0 + 1 < Wl) ? fy * aw        : 0.f;
        int x0c = min(max(x0, 0), Wl - 1);
        int x1c = min(max(x0 + 1, 0), Wl - 1);
        int y0c = min(max(y0, 0), Wl - 1);
        int y1c = min(max(y0 + 1, 0), Wl - 1);
        int r0i = st + y0c * Wl, r1i = st + y1c * Wl;
        s_off[tid][0] = (uint32_t)(r0i + x0c) << 8;
        s_off[tid][1] = (uint32_t)(r0i + x1c) << 8;
        s_off[tid][2] = (uint32_t)(r1i + x0c) << 8;
        s_off[tid][3] = (uint32_t)(r1i + x1c) << 8;
        __half2 w0 = __floats2half2_rn(wx0 * wy0, wx0 * wy0);
        __half2 w1 = __floats2half2_rn(wx1 * wy0, wx1 * wy0);
        __half2 w2 = __floats2half2_rn(wx0 * wy1, wx0 * wy1);
        __half2 w3 = __floats2half2_rn(wx1 * wy1, wx1 * wy1);
        s_w[tid][0] = *reinterpret_cast<uint32_t*>(&w0);
        s_w[tid][1] = *reinterpret_cast<uint32_t*>(&w1);
        s_w[tid][2] = *reinterpret_cast<uint32_t*>(&w2);
        s_w[tid][3] = *reinterpret_cast<uint32_t*>(&w3);
    }
    __syncthreads();

    int h    = tid >> 5;
    int lane = tid & 31;
    int ch   = lane & 15;
    int half = lane >> 4;
    // both tokens share one batch (row0 even, NTOK even) -> hoist vb
    int b = (row0 >= NTOK) ? 1 : 0;
    const uint8_t* vb = value + ((size_t)b * NTOK) * 256 + h * 32 + ch * 2;

    #pragma unroll
    for (int tok = 0; tok < 2; tok++) {
        int row = row0 + tok;
        __half2 acc = __floats2half2_rn(0.f, 0.f);
        #pragma unroll
        for (int j = 0; j < 8; j++) {
            int e = tok * 128 + h * 16 + j * 2 + half;
            uint4 off = *(const uint4*)(&s_off[e][0]);
            uint4 ww  = *(const uint4*)(&s_w[e][0]);
            __half2 f0 = e4h2(*(const uint16_t*)(vb + off.x));
            __half2 f1 = e4h2(*(const uint16_t*)(vb + off.y));
            __half2 f2 = e4h2(*(const uint16_t*)(vb + off.z));
            __half2 f3 = e4h2(*(const uint16_t*)(vb + off.w));
            acc = __hfma2(u2h2(ww.x), f0, acc);
            acc = __hfma2(u2h2(ww.y), f1, acc);
            acc = __hfma2(u2h2(ww.z), f2, acc);
            acc = __hfma2(u2h2(ww.w), f3, acc);
        }
        float2 a = __half22float2(acc);
        a.x += __shfl_xor_sync(0xffffffffu, a.x, 16);
        a.y += __shfl_xor_sync(0xffffffffu, a.y, 16);
        if (half == 0) {
            uint32_t* sp = (uint32_t*)(samp + (size_t)row * 256 + h * 32);
            sp[ch] = pack_bf2(a.x * VAL_DESCALE, a.y * VAL_DESCALE);
        }
    }
}

// =============================== launcher ====================================
extern "C" void kernel_launch(void* const* d_in, const int* in_sizes, int n_in,
                              void* d_out, int out_size)
{
    (void)n_in;
    const float* src[4];
    const float* pos[4];
    bool interleaved = (in_sizes[1] == in_sizes[0]);
    for (int i = 0; i < 4; i++) {
        if (interleaved) { src[i] = (const float*)d_in[2*i];
                           pos[i] = (const float*)d_in[2*i+1]; }
        else             { src[i] = (const float*)d_in[i];
                           pos[i] = (const float*)d_in[4+i]; }
    }
    const float* level_embed = (const float*)d_in[8];
    const float* W_off  = (const float*)d_in[9];
    const float* b_off  = (const float*)d_in[10];
    const float* W_attn = (const float*)d_in[11];
    const float* b_attn = (const float*)d_in[12];
    const float* W_val  = (const float*)d_in[13];
    const float* b_val  = (const float*)d_in[14];
    const float* W_out  = (const float*)d_in[15];
    const float* b_out  = (const float*)d_in[16];
    const float* g_na   = (const float*)d_in[17];
    const float* g_nf   = (const float*)d_in[18];
    const float* ls_a   = (const float*)d_in[19];
    const float* ls_f   = (const float*)d_in[20];
    const float* W1     = (const float*)d_in[21];
    const float* b1     = (const float*)d_in[22];
    const float* W3     = (const float*)d_in[23];
    const float* b3     = (const float*)d_in[24];
    const float* W2     = (const float*)d_in[25];
    const float* b2     = (const float*)d_in[26];

    float *q, *boa, *bg;
    bf16 *posf, *nbuf, *qin, *oab, *sampb, *h1;
    uint8_t *val8;
    bf16 *woa, *wval, *wout, *wg, *w2;
    cudaGetSymbolAddress((void**)&q,     g_q);
    cudaGetSymbolAddress((void**)&posf,  g_posf);
    cudaGetSymbolAddress((void**)&nbuf,  g_n);
    cudaGetSymbolAddress((void**)&qin,   g_qin);
    cudaGetSymbolAddress((void**)&val8,  g_val8);
    cudaGetSymbolAddress((void**)&oab,   g_oa);
    cudaGetSymbolAddress((void**)&sampb, g_samp);
    cudaGetSymbolAddress((void**)&h1,    g_h1);
    cudaGetSymbolAddress((void**)&woa,   g_woa);
    cudaGetSymbolAddress((void**)&boa,   g_boa);
    cudaGetSymbolAddress((void**)&wval,  g_wval);
    cudaGetSymbolAddress((void**)&wout,  g_wout);
    cudaGetSymbolAddress((void**)&wg,    g_wg);
    cudaGetSymbolAddress((void**)&bg,    g_bg);
    cudaGetSymbolAddress((void**)&w2,    g_w2);

    cudaFuncSetAttribute((const void*)hgemm<1>, cudaFuncAttributeMaxDynamicSharedMemorySize, SMEM_TOTAL_GEMM);
    cudaFuncSetAttribute((const void*)hgemm<4>, cudaFuncAttributeMaxDynamicSharedMemorySize, SMEM_TOTAL_GEMM);
    cudaFuncSetAttribute((const void*)hgemm<5>, cudaFuncAttributeMaxDynamicSharedMemorySize, SMEM_TOTAL_GEMM);
    cudaFuncSetAttribute((const void*)hgemm<6>, cudaFuncAttributeMaxDynamicSharedMemorySize, SMEM_TOTAL_GEMM);

    Ptrs8 ps;
    for (int l = 0; l < 4; l++) { ps.p[l] = src[l]; ps.p[4 + l] = pos[l]; }
    PrepArgs pa = { W_off, W_attn, b_off, b_attn, W_val, W_out,
                    W1, W3, b1, b3, W2,
                    woa, boa, wval, wout, wg, bg, w2,
                    (float*)d_out, out_size };

    const int MT = NQ / 128;
    dim3 g2(2, MT), g5(5, MT), g16(16, MT);
    const int SB = SMEM_TOTAL_GEMM;

    transpose_prep<<<dim3(NTOK / 32, DIM / 32, BATCH * 2), dim3(32, 8)>>>(
        ps, level_embed, q, posf, pa);

    for (int i = 0; i < NLAY; i++) {
        rms_kernel<<<NQ / 8, 256>>>(q, g_na + i * DIM, posf, nbuf, qin);
        hgemm<5><<<g5, 256, SB>>>(256, 256,
            nbuf, wval + (size_t)i*65536, b_val + i*256, val8, nullptr,
            qin,  woa  + (size_t)i*98304, boa + i*384, oab);
        msda_kernel<<<NQ / 2, 256>>>(oab, val8, sampb);
        hgemm<1><<<g2, 256, SB>>>(256, 256, sampb, wout + (size_t)i*65536,
                                  b_out + i*256, q, ls_a + i*256,
                                  nullptr, nullptr, nullptr, nullptr);
        rms_kernel<<<NQ / 8, 256>>>(q, g_nf + i * DIM, nullptr, nbuf, nullptr);
        hgemm<4><<<g16, 256, SB>>>(2048, 256, nbuf, wg + (size_t)i*524288,
                                   bg + i*2048, h1, nullptr,
                                   nullptr, nullptr, nullptr, nullptr);
        if (i < NLAY - 1) {
            hgemm<1><<<g2, 256, SB>>>(256, DFFN, h1, w2 + (size_t)i*262144,
                                      b2 + i*256, q, ls_f + i*256,
                                      nullptr, nullptr, nullptr, nullptr);
        } else {
            hgemm<6><<<g2, 256, SB>>>(256, DFFN, h1, w2 + (size_t)i*262144,
                                      b2 + i*256, q, ls_f + i*256,
                                      nullptr, nullptr, nullptr, (float*)d_out);
        }
    }
}

// round 17
// speedup vs baseline: 1.0117x; 1.0014x over previous
#include <cuda_runtime.h>
#include <cuda_bf16.h>
#include <cuda_fp16.h>
#include <cstdint>
#include <math.h>

#define NTOK   21760
#define BATCH  2
#define NQ     (NTOK*BATCH)
#define DIM    256
#define NLAY   6
#define DFFN   1024
#define QOUT   (NQ*DIM)

typedef __nv_bfloat16 bf16;

__device__ __constant__ int c_LW[4] = {128, 64, 32, 16};
__device__ __constant__ int c_LS[4] = {0, 16384, 20480, 21504};
__device__ __constant__ float c_tail[12] = {128.f,128.f,64.f,64.f,32.f,32.f,16.f,16.f,
                                            0.f,16384.f,20480.f,21504.f};

// scratch (device globals; allocation-free)
__device__ __align__(256) float   g_q   [NQ*DIM];
__device__ __align__(256) bf16    g_posf[NQ*DIM];
__device__ __align__(256) bf16    g_n   [NQ*DIM];
__device__ __align__(256) bf16    g_qin [NQ*DIM];
__device__ __align__(256) uint8_t g_val8[NQ*DIM];
__device__ __align__(256) bf16    g_oa  [NQ*384];
__device__ __align__(256) bf16    g_samp[NQ*DIM];
__device__ __align__(256) bf16    g_h1  [NQ*DFFN];
__device__ __align__(256) bf16    g_woa  [NLAY*384*256];
__device__ __align__(256) float   g_boa  [NLAY*384];
__device__ __align__(256) bf16    g_wval [NLAY*256*256];
__device__ __align__(256) bf16    g_wout [NLAY*256*256];
__device__ __align__(256) bf16    g_wg   [NLAY*2048*256];
__device__ __align__(256) float   g_bg   [NLAY*2048];
__device__ __align__(256) bf16    g_w2   [NLAY*256*DFFN];

// ---------------- PTX helpers --------------------------------------------
__device__ __forceinline__ uint32_t smem_u32(const void* p) {
    uint32_t a;
    asm("{ .reg .u64 t; cvta.to.shared.u64 t, %1; cvt.u32.u64 %0, t; }"
        : "=r"(a) : "l"(p));
    return a;
}
#define CPASYNC16(saddr, gptr) \
    asm volatile("cp.async.cg.shared.global [%0], [%1], 16;" \
                 :: "r"(saddr), "l"(gptr))
#define CPASYNC_COMMIT() asm volatile("cp.async.commit_group;" ::: "memory")
#define CPASYNC_WAIT(n)  asm volatile("cp.async.wait_group %0;" :: "n"(n) : "memory")
#define LDSM4(d0,d1,d2,d3,addr) \
    asm volatile("ldmatrix.sync.aligned.m8n8.x4.shared.b16 {%0,%1,%2,%3}, [%4];" \
                 : "=r"(d0),"=r"(d1),"=r"(d2),"=r"(d3) : "r"(addr))
#define MMA16816(c, a, b0, b1) \
    asm volatile("mma.sync.aligned.m16n8k16.row.col.f32.bf16.bf16.f32 " \
                 "{%0,%1,%2,%3},{%4,%5,%6,%7},{%8,%9},{%0,%1,%2,%3};" \
                 : "+f"((c)[0]),"+f"((c)[1]),"+f"((c)[2]),"+f"((c)[3]) \
                 : "r"((a)[0]),"r"((a)[1]),"r"((a)[2]),"r"((a)[3]), \
                   "r"(b0),"r"(b1))
#define SWZ128(off) ((off) ^ (((off) >> 3) & 0x70))

__device__ __forceinline__ uint32_t pack_bf2(float a, float b) {
    __nv_bfloat162 h = __floats2bfloat162_rn(a, b);
    return *reinterpret_cast<uint32_t*>(&h);
}
__device__ __forceinline__ uint16_t pk_e4m3(float lo, float hi) {
    uint16_t r;
    asm("cvt.rn.satfinite.e4m3x2.f32 %0, %1, %2;" : "=h"(r) : "f"(hi), "f"(lo));
    return r;
}
__device__ __forceinline__ __half2 e4h2(uint16_t u) {
    uint32_t h;
    asm("cvt.rn.f16x2.e4m3x2 %0, %1;" : "=r"(h) : "h"(u));
    return *reinterpret_cast<__half2*>(&h);
}
__device__ __forceinline__ __half2 u2h2(uint32_t u) {
    return *reinterpret_cast<__half2*>(&u);
}
__device__ __forceinline__ float2 bf2f(uint32_t u) {
    return __bfloat1622float2(*reinterpret_cast<__nv_bfloat162*>(&u));
}

#define VAL_SCALE   8.0f
#define VAL_DESCALE 0.125f

// ================= bf16 tensor-core GEMM =====================================
// EPI 1: C[f32] += ls[n]*v            (in-place residual)
// EPI 4: GLU: h1[m, n/2] = silu(v_even)*v_odd (bf16, width Nc/2)
// EPI 5: merged: tiles 0-1 -> val fp8 x8; tiles 2-4 -> oa bf16
// EPI 6: final: Cv2[f32] = Cv[f32] + ls[n]*v  (writes d_out only)
#define STAGE_BYTES 32768
#define SMEM_TOTAL_GEMM (3*STAGE_BYTES)

template<int EPI>
__global__ void __launch_bounds__(256, 2)
hgemm(int Nc, int K,
      const bf16* __restrict__ A, const bf16* __restrict__ B,
      const float* __restrict__ bias, void* __restrict__ Cv,
      const float* __restrict__ ls,
      const bf16* __restrict__ A2, const bf16* __restrict__ B2,
      const float* __restrict__ bias2, void* __restrict__ Cv2)
{
    extern __shared__ uint8_t dsm[];
    const uint32_t s0 = smem_u32(dsm);

    const int tid = threadIdx.x;
    const int lane = tid & 31, wid = tid >> 5;
    const int warp_m = wid >> 2, warp_n = wid & 3;
    const int bn = blockIdx.x, bm = blockIdx.y;
    const int NCH = K >> 6;

    const bf16* Ause = A;  const bf16* Buse = B;
    const float* biasuse = bias;
    void* Cuse = Cv;
    int NcU = Nc, bnl = bn;
    if (EPI == 5 && bn >= 2) {
        Ause = A2; Buse = B2; biasuse = bias2; Cuse = Cv2;
        NcU = 384; bnl = bn - 2;
    }

    const bf16* Ag = Ause + (size_t)(bm * 128) * K;
    const bf16* Bg = Buse + (size_t)(bnl * 128) * K;

    auto issue = [&](int c, int s) {
        uint32_t sa = s0 + s * STAGE_BYTES;
        uint32_t sb = sa + 16384;
        const bf16* Agp = Ag + c * 64;
        const bf16* Bgp = Bg + c * 64;
        #pragma unroll
        for (int j = 0; j < 4; j++) {
            int idx = tid + 256 * j;
            int row = idx >> 3, q = idx & 7;
            CPASYNC16(sa + SWZ128(row * 128 + q * 16),
                      Agp + (size_t)row * K + q * 8);
        }
        #pragma unroll
        for (int j = 0; j < 4; j++) {
            int idx = tid + 256 * j;
            int row = idx >> 3, q = idx & 7;
            CPASYNC16(sb + SWZ128(row * 128 + q * 16),
                      Bgp + (size_t)row * K + q * 8);
        }
        CPASYNC_COMMIT();
    };

    float acc[4][4][4];
    #pragma unroll
    for (int i = 0; i < 4; i++)
        #pragma unroll
        for (int j = 0; j < 4; j++)
            #pragma unroll
            for (int k = 0; k < 4; k++) acc[i][j][k] = 0.f;

    const int mat = lane >> 3, r8 = lane & 7;

    issue(0, 0);
    issue(1, 1);
    int s = 0;
    for (int c = 0; c < NCH; c++) {
        if (c + 1 < NCH) { CPASYNC_WAIT(1); } else { CPASYNC_WAIT(0); }
        __syncthreads();
        if (c + 2 < NCH) issue(c + 2, (s + 2) % 3);

        uint32_t sa = s0 + s * STAGE_BYTES;
        uint32_t sb = sa + 16384;
        #pragma unroll
        for (int ks = 0; ks < 4; ks++) {
            uint32_t a[4][4], bfr[4][2];
            #pragma unroll
            for (int mt = 0; mt < 4; mt++) {
                int row = warp_m * 64 + mt * 16 + (mat & 1) * 8 + r8;
                int kb  = ks * 32 + (mat >> 1) * 16;
                LDSM4(a[mt][0], a[mt][1], a[mt][2], a[mt][3],
                      sa + SWZ128(row * 128 + kb));
            }
            #pragma unroll
            for (int np = 0; np < 2; np++) {
                int nrow = warp_n * 32 + np * 16 + (mat >> 1) * 8 + r8;
                int kb   = ks * 32 + (mat & 1) * 16;
                uint32_t t0, t1, t2, t3;
                LDSM4(t0, t1, t2, t3, sb + SWZ128(nrow * 128 + kb));
                bfr[np*2+0][0] = t0; bfr[np*2+0][1] = t1;
                bfr[np*2+1][0] = t2; bfr[np*2+1][1] = t3;
            }
            #pragma unroll
            for (int mt = 0; mt < 4; mt++)
                #pragma unroll
                for (int nt = 0; nt < 4; nt++)
                    MMA16816(acc[mt][nt], a[mt], bfr[nt][0], bfr[nt][1]);
        }
        s = (s + 1) % 3;
    }

    const int g  = lane >> 2, tg = lane & 3;
    const int rbase = bm * 128 + warp_m * 64;
    const int cbase = bnl * 128 + warp_n * 32;

    #pragma unroll
    for (int mt = 0; mt < 4; mt++) {
        #pragma unroll
        for (int nt = 0; nt < 4; nt++) {
            int col = cbase + nt * 8 + tg * 2;
            float2 bs2 = *(const float2*)(biasuse + col);
            int r0 = rbase + mt * 16 + g;
            float v00 = acc[mt][nt][0] + bs2.x, v01 = acc[mt][nt][1] + bs2.y;
            float v10 = acc[mt][nt][2] + bs2.x, v11 = acc[mt][nt][3] + bs2.y;

            if (EPI == 4) {
                int j = col >> 1;
                int ncout = Nc >> 1;
                float g0 = (v00 / (1.f + __expf(-v00))) * v01;
                float g1 = (v10 / (1.f + __expf(-v10))) * v11;
                bf16* Cb = (bf16*)Cuse;
                Cb[(size_t)r0 * ncout + j]       = __float2bfloat16(g0);
                Cb[(size_t)(r0 + 8) * ncout + j] = __float2bfloat16(g1);
            } else {
                size_t i0 = (size_t)r0 * NcU + col;
                size_t i1 = (size_t)(r0 + 8) * NcU + col;
                if (EPI == 1) {
                    float2 ls2 = *(const float2*)(ls + col);
                    float* Cf = (float*)Cuse;
                    float2 q0 = *(float2*)(Cf + i0);
                    float2 q1 = *(float2*)(Cf + i1);
                    q0.x += ls2.x * v00; q0.y += ls2.y * v01;
                    q1.x += ls2.x * v10; q1.y += ls2.y * v11;
                    *(float2*)(Cf + i0) = q0;
                    *(float2*)(Cf + i1) = q1;
                } else if (EPI == 6) {
                    float2 ls2 = *(const float2*)(ls + col);
                    const float* Qf = (const float*)Cuse;
                    float* Of = (float*)Cv2;
                    float2 q0 = *(const float2*)(Qf + i0);
                    float2 q1 = *(const float2*)(Qf + i1);
                    q0.x += ls2.x * v00; q0.y += ls2.y * v01;
                    q1.x += ls2.x * v10; q1.y += ls2.y * v11;
                    *(float2*)(Of + i0) = q0;
                    *(float2*)(Of + i1) = q1;
                } else if (EPI == 5 && bn < 2) {
                    uint8_t* Cb = (uint8_t*)Cuse;
                    *(uint16_t*)(Cb + i0) = pk_e4m3(v00 * VAL_SCALE, v01 * VAL_SCALE);
                    *(uint16_t*)(Cb + i1) = pk_e4m3(v10 * VAL_SCALE, v11 * VAL_SCALE);
                } else {
                    bf16* Cb = (bf16*)Cuse;
                    *(uint32_t*)(Cb + i0) = pack_bf2(v00, v01);
                    *(uint32_t*)(Cb + i1) = pack_bf2(v10, v11);
                }
            }
        }
    }
}

// ---------------- transpose + weight prep + output tail (single launch) -----
struct Ptrs8 { const float* p[8]; };
struct PrepArgs {
    const float *Woff, *Wattn, *boff, *battn, *Wval, *Wout;
    const float *W1, *W3, *b1, *b3, *W2;
    bf16 *woa; float *boa; bf16 *wval, *wout, *wg; float *bg; bf16 *w2;
    float *out; int out_size;
};

__global__ void __launch_bounds__(256)
transpose_prep(Ptrs8 ps, const float* __restrict__ le,
               float* __restrict__ dq, bf16* __restrict__ dp, PrepArgs pa)
{
    __shared__ float tile[32][33];
    int p0 = blockIdx.x * 32;
    int d0 = blockIdx.y * 32;
    int bz = blockIdx.z;
    int b = bz >> 1, t = bz & 1;
    int tx = threadIdx.x, ty = threadIdx.y;

    int lvl = (p0 >= 21504) ? 3 : (p0 >= 20480) ? 2 : (p0 >= 16384) ? 1 : 0;
    int HW  = c_LW[lvl] * c_LW[lvl];
    int loc = p0 - c_LS[lvl];

    const float* s = ps.p[t * 4 + lvl] + ((size_t)b * DIM + d0) * HW + loc;
    #pragma unroll
    for (int i = ty; i < 32; i += 8)
        tile[i][tx] = s[(size_t)i * HW + tx];
    __syncthreads();
    #pragma unroll
    for (int i = ty; i < 32; i += 8) {
        float v = tile[tx][i];
        size_t di = ((size_t)b * NTOK + p0 + i) * DIM + d0 + tx;
        if (t) dp[di] = __float2bfloat16(v + le[lvl * DIM + d0 + tx]);
        else   dq[di] = v;
    }

    if (bz != 0) return;
    int t0 = (blockIdx.y * gridDim.x + blockIdx.x) * 256 + ty * 32 + tx;
    int stride = gridDim.x * gridDim.y * 256;

    for (int i = t0; i < pa.out_size - QOUT; i += stride)
        pa.out[QOUT + i] = (i < 12) ? c_tail[i] : 0.f;

    for (int i = t0; i < NLAY*384*256; i += stride) {
        int layer = i / (384*256);
        int rem = i - layer * 384*256;
        int r = rem >> 8, k = rem & 255;
        float v = (r < 256) ? pa.Woff[layer*65536 + r*256 + k]
                            : pa.Wattn[layer*32768 + (r-256)*256 + k];
        pa.woa[i] = __float2bfloat16(v);
    }
    for (int i = t0; i < NLAY*384; i += stride) {
        int layer = i / 384, r = i - layer * 384;
        pa.boa[i] = (r < 256) ? pa.boff[layer*256 + r]
                              : pa.battn[layer*128 + (r-256)];
    }
    for (int i = t0; i < NLAY*256*256; i += stride) {
        pa.wval[i] = __float2bfloat16(pa.Wval[i]);
        pa.wout[i] = __float2bfloat16(pa.Wout[i]);
    }
    for (int i = t0; i < NLAY*2048*256; i += stride) {
        int layer = i / (2048*256);
        int rem = i - layer * 2048*256;
        int r = rem >> 8, k = rem & 255;
        int j = r >> 1, sel = r & 1;
        const float* Wsrc = sel ? pa.W3 : pa.W1;
        pa.wg[i] = __float2bfloat16(Wsrc[(size_t)layer*DFFN*256 + j*256 + k]);
    }
    for (int i = t0; i < NLAY*2048; i += stride) {
        int layer = i / 2048, r = i - layer * 2048;
        int j = r >> 1, sel = r & 1;
        pa.bg[i] = sel ? pa.b3[layer*DFFN + j] : pa.b1[layer*DFFN + j];
    }
    for (int i = t0; i < NLAY*256*DFFN; i += stride)
        pa.w2[i] = __float2bfloat16(pa.W2[i]);
}

// ---------------- RMSNorm (fp32 q in, bf16 posf) -> bf16 n (+ bf16 qin) -----
__global__ void __launch_bounds__(256)
rms_kernel(const float* __restrict__ x, const float* __restrict__ g,
           const bf16* __restrict__ posf, bf16* __restrict__ out_n,
           bf16* __restrict__ out_qin)
{
    int warp = threadIdx.x >> 5, lane = threadIdx.x & 31;
    int row  = blockIdx.x * 8 + warp;
    const float* xr = x + (size_t)row * DIM;

    float4 v0 = *(const float4*)(xr + lane * 4);
    float4 v1 = *(const float4*)(xr + 128 + lane * 4);
    float s = v0.x*v0.x + v0.y*v0.y + v0.z*v0.z + v0.w*v0.w
            + v1.x*v1.x + v1.y*v1.y + v1.z*v1.z + v1.w*v1.w;
    #pragma unroll
    for (int o = 16; o; o >>= 1) s += __shfl_xor_sync(0xffffffffu, s, o);
    float scale = rsqrtf(s * (1.0f / 256.0f) + 1e-6f);

    float4 ga = *(const float4*)(g + lane * 4);
    float4 gb = *(const float4*)(g + 128 + lane * 4);
    float n0x = v0.x*scale*ga.x, n0y = v0.y*scale*ga.y;
    float n0z = v0.z*scale*ga.z, n0w = v0.w*scale*ga.w;
    float n1x = v1.x*scale*gb.x, n1y = v1.y*scale*gb.y;
    float n1z = v1.z*scale*gb.z, n1w = v1.w*scale*gb.w;

    bf16* nr = out_n + (size_t)row * DIM;
    *(uint2*)(nr + lane * 4)       = make_uint2(pack_bf2(n0x, n0y), pack_bf2(n0z, n0w));
    *(uint2*)(nr + 128 + lane * 4) = make_uint2(pack_bf2(n1x, n1y), pack_bf2(n1z, n1w));

    if (out_qin) {
        const bf16* pr = posf + (size_t)row * DIM;
        uint2 pa2 = *(const uint2*)(pr + lane * 4);
        uint2 pb2 = *(const uint2*)(pr + 128 + lane * 4);
        float2 p0 = bf2f(pa2.x), p1 = bf2f(pa2.y);
        float2 p2 = bf2f(pb2.x), p3 = bf2f(pb2.y);
        bf16* qr = out_qin + (size_t)row * DIM;
        *(uint2*)(qr + lane * 4) =
            make_uint2(pack_bf2(n0x + p0.x, n0y + p0.y), pack_bf2(n0z + p1.x, n0w + p1.y));
        *(uint2*)(qr + 128 + lane * 4) =
            make_uint2(pack_bf2(n1x + p2.x, n1y + p2.y), pack_bf2(n1z + p3.x, n1w + p3.y));
    }
}

// ---------------- deformable sampling: 2 tokens/block, 2-phase ---------------
__global__ void __launch_bounds__(256)
msda_kernel(const bf16* __restrict__ oa, const uint8_t* __restrict__ value,
            bf16* __restrict__ samp)
{
    __shared__ __align__(16) uint32_t s_off[256][4];
    __shared__ __align__(16) uint32_t s_w  [256][4];

    int row0 = blockIdx.x * 2;
    int tid = threadIdx.x;

    {
        int tok = tid >> 7, tt = tid & 127;
        int row = row0 + tok;
        int b = row / NTOK;
        int n = row - b * NTOK;
        int h = tt >> 4, p = tt & 15;

        float lg = __bfloat162float(oa[(size_t)row * 384 + 256 + h * 16 + p]);
        float mx = lg;
        #pragma unroll
        for (int o = 8; o; o >>= 1)
            mx = fmaxf(mx, __shfl_xor_sync(0xffffffffu, mx, o));
        float e = __expf(lg - mx);
        float ssum = e;
        #pragma unroll
        for (int o = 8; o; o >>= 1)
            ssum += __shfl_xor_sync(0xffffffffu, ssum, o);
        float aw = e / ssum;

        int lvq = (n >= 21504) ? 3 : (n >= 20480) ? 2 : (n >= 16384) ? 1 : 0;
        int Wq  = c_LW[lvq];
        int li  = n - c_LS[lvq];
        int iy  = li / Wq, ix = li - iy * Wq;
        float refx = (ix + 0.5f) / (float)Wq;
        float refy = (iy + 0.5f) / (float)Wq;

        int l  = p >> 2;
        int Wl = c_LW[l], st = c_LS[l];
        float fW = (float)Wl;
        float2 o2 = __bfloat1622float2(
            *(const __nv_bfloat162*)(oa + (size_t)row * 384 + h * 32 + p * 2));
        float xx = (refx + o2.x / fW) * fW - 0.5f;
        float yy = (refy + o2.y / fW) * fW - 0.5f;
        float x0f = floorf(xx), y0f = floorf(yy);
        int x0 = (int)x0f, y0 = (int)y0f;
        float fx = xx - x0f, fy = yy - y0f;
        float wx0 = (x0 >= 0     && x0 < Wl)     ? (1.f - fx) : 0.f;
        float wx1 = (x0 + 1 >= 0 && x0 + 1 < Wl) ? fx         : 0.f;
        float wy0 = (y0 >= 0     && y0 < Wl)     ? (1.f - fy) * aw : 0.f;
        float wy1 = (y0 + 1 >= 0 && y0 + 1 < Wl) ? fy * aw        : 0.f;
        int x0c = min(max(x0, 0), Wl - 1);
        int x1c = min(max(x0 + 1, 0), Wl - 1);
        int y0c = min(max(y0, 0), Wl - 1);
        int y1c = min(max(y0 + 1, 0), Wl - 1);
        int r0i = st + y0c * Wl, r1i = st + y1c * Wl;
        s_off[tid][0] = (uint32_t)(r0i + x0c) << 8;
        s_off[tid][1] = (uint32_t)(r0i + x1c) << 8;
        s_off[tid][2] = (uint32_t)(r1i + x0c) << 8;
        s_off[tid][3] = (uint32_t)(r1i + x1c) << 8;
        __half2 w0 = __floats2half2_rn(wx0 * wy0, wx0 * wy0);
        __half2 w1 = __floats2half2_rn(wx1 * wy0, wx1 * wy0);
        __half2 w2 = __floats2half2_rn(wx0 * wy1, wx0 * wy1);
        __half2 w3 = __floats2half2_rn(wx1 * wy1, wx1 * wy1);
        s_w[tid][0] = *reinterpret_cast<uint32_t*>(&w0);
        s_w[tid][1] = *reinterpret_cast<uint32_t*>(&w1);
        s_w[tid][2] = *reinterpret_cast<uint32_t*>(&w2);
        s_w[tid][3] = *reinterpret_cast<uint32_t*>(&w3);
    }
    __syncthreads();

    int h    = tid >> 5;
    int lane = tid & 31;
    int ch   = lane & 15;
    int half = lane >> 4;

    #pragma unroll
    for (int tok = 0; tok < 2; tok++) {
        int row = row0 + tok;
        int b = row / NTOK;
        const uint8_t* vb = value + ((size_t)b * NTOK) * 256 + h * 32 + ch * 2;

        __half2 acc = __floats2half2_rn(0.f, 0.f);
        #pragma unroll
        for (int j = 0; j < 8; j++) {
            int e = tok * 128 + h * 16 + j * 2 + half;
            uint4 off = *(const uint4*)(&s_off[e][0]);
            uint4 ww  = *(const uint4*)(&s_w[e][0]);
            __half2 f0 = e4h2(*(const uint16_t*)(vb + off.x));
            __half2 f1 = e4h2(*(const uint16_t*)(vb + off.y));
            __half2 f2 = e4h2(*(const uint16_t*)(vb + off.z));
            __half2 f3 = e4h2(*(const uint16_t*)(vb + off.w));
            acc = __hfma2(u2h2(ww.x), f0, acc);
            acc = __hfma2(u2h2(ww.y), f1, acc);
            acc = __hfma2(u2h2(ww.z), f2, acc);
            acc = __hfma2(u2h2(ww.w), f3, acc);
        }
        float2 a = __half22float2(acc);
        a.x += __shfl_xor_sync(0xffffffffu, a.x, 16);
        a.y += __shfl_xor_sync(0xffffffffu, a.y, 16);
        if (half == 0) {
            uint32_t* sp = (uint32_t*)(samp + (size_t)row * 256 + h * 32);
            sp[ch] = pack_bf2(a.x * VAL_DESCALE, a.y * VAL_DESCALE);
        }
    }
}

// =============================== launcher ====================================
extern "C" void kernel_launch(void* const* d_in, const int* in_sizes, int n_in,
                              void* d_out, int out_size)
{
    (void)n_in;
    const float* src[4];
    const float* pos[4];
    bool interleaved = (in_sizes[1] == in_sizes[0]);
    for (int i = 0; i < 4; i++) {
        if (interleaved) { src[i] = (const float*)d_in[2*i];
                           pos[i] = (const float*)d_in[2*i+1]; }
        else             { src[i] = (const float*)d_in[i];
                           pos[i] = (const float*)d_in[4+i]; }
    }
    const float* level_embed = (const float*)d_in[8];
    const float* W_off  = (const float*)d_in[9];
    const float* b_off  = (const float*)d_in[10];
    const float* W_attn = (const float*)d_in[11];
    const float* b_attn = (const float*)d_in[12];
    const float* W_val  = (const float*)d_in[13];
    const float* b_val  = (const float*)d_in[14];
    const float* W_out  = (const float*)d_in[15];
    const float* b_out  = (const float*)d_in[16];
    const float* g_na   = (const float*)d_in[17];
    const float* g_nf   = (const float*)d_in[18];
    const float* ls_a   = (const float*)d_in[19];
    const float* ls_f   = (const float*)d_in[20];
    const float* W1     = (const float*)d_in[21];
    const float* b1     = (const float*)d_in[22];
    const float* W3     = (const float*)d_in[23];
    const float* b3     = (const float*)d_in[24];
    const float* W2     = (const float*)d_in[25];
    const float* b2     = (const float*)d_in[26];

    float *q, *boa, *bg;
    bf16 *posf, *nbuf, *qin, *oab, *sampb, *h1;
    uint8_t *val8;
    bf16 *woa, *wval, *wout, *wg, *w2;
    cudaGetSymbolAddress((void**)&q,     g_q);
    cudaGetSymbolAddress((void**)&posf,  g_posf);
    cudaGetSymbolAddress((void**)&nbuf,  g_n);
    cudaGetSymbolAddress((void**)&qin,   g_qin);
    cudaGetSymbolAddress((void**)&val8,  g_val8);
    cudaGetSymbolAddress((void**)&oab,   g_oa);
    cudaGetSymbolAddress((void**)&sampb, g_samp);
    cudaGetSymbolAddress((void**)&h1,    g_h1);
    cudaGetSymbolAddress((void**)&woa,   g_woa);
    cudaGetSymbolAddress((void**)&boa,   g_boa);
    cudaGetSymbolAddress((void**)&wval,  g_wval);
    cudaGetSymbolAddress((void**)&wout,  g_wout);
    cudaGetSymbolAddress((void**)&wg,    g_wg);
    cudaGetSymbolAddress((void**)&bg,    g_bg);
    cudaGetSymbolAddress((void**)&w2,    g_w2);

    cudaFuncSetAttribute((const void*)hgemm<1>, cudaFuncAttributeMaxDynamicSharedMemorySize, SMEM_TOTAL_GEMM);
    cudaFuncSetAttribute((const void*)hgemm<4>, cudaFuncAttributeMaxDynamicSharedMemorySize, SMEM_TOTAL_GEMM);
    cudaFuncSetAttribute((const void*)hgemm<5>, cudaFuncAttributeMaxDynamicSharedMemorySize, SMEM_TOTAL_GEMM);
    cudaFuncSetAttribute((const void*)hgemm<6>, cudaFuncAttributeMaxDynamicSharedMemorySize, SMEM_TOTAL_GEMM);

    Ptrs8 ps;
    for (int l = 0; l < 4; l++) { ps.p[l] = src[l]; ps.p[4 + l] = pos[l]; }
    PrepArgs pa = { W_off, W_attn, b_off, b_attn, W_val, W_out,
                    W1, W3, b1, b3, W2,
                    woa, boa, wval, wout, wg, bg, w2,
                    (float*)d_out, out_size };

    const int MT = NQ / 128;
    dim3 g2(2, MT), g5(5, MT), g16(16, MT);
    const int SB = SMEM_TOTAL_GEMM;

    transpose_prep<<<dim3(NTOK / 32, DIM / 32, BATCH * 2), dim3(32, 8)>>>(
        ps, level_embed, q, posf, pa);

    for (int i = 0; i < NLAY; i++) {
        rms_kernel<<<NQ / 8, 256>>>(q, g_na + i * DIM, posf, nbuf, qin);
        hgemm<5><<<g5, 256, SB>>>(256, 256,
            nbuf, wval + (size_t)i*65536, b_val + i*256, val8, nullptr,
            qin,  woa  + (size_t)i*98304, boa + i*384, oab);
        msda_kernel<<<NQ / 2, 256>>>(oab, val8, sampb);
        hgemm<1><<<g2, 256, SB>>>(256, 256, sampb, wout + (size_t)i*65536,
                                  b_out + i*256, q, ls_a + i*256,
                                  nullptr, nullptr, nullptr, nullptr);
        rms_kernel<<<NQ / 8, 256>>>(q, g_nf + i * DIM, nullptr, nbuf, nullptr);
        hgemm<4><<<g16, 256, SB>>>(2048, 256, nbuf, wg + (size_t)i*524288,
                                   bg + i*2048, h1, nullptr,
                                   nullptr, nullptr, nullptr, nullptr);
        if (i < NLAY - 1) {
            hgemm<1><<<g2, 256, SB>>>(256, DFFN, h1, w2 + (size_t)i*262144,
                                      b2 + i*256, q, ls_f + i*256,
                                      nullptr, nullptr, nullptr, nullptr);
        } else {
            hgemm<6><<<g2, 256, SB>>>(256, DFFN, h1, w2 + (size_t)i*262144,
                                      b2 + i*256, q, ls_f + i*256,
                                      nullptr, nullptr, nullptr, (float*)d_out);
        }
    }
}